// round 2
// baseline (speedup 1.0000x reference)
#include <cuda_runtime.h>
#include <math.h>

// x: (256, 2048, 25, 2) fp32 contiguous -> 26,214,400 floats -> 6,553,600 float4
// weights: (2048, 1) fp32; only weights[0] is used (faithful to reference).
//
// Each float4 holds two (x,y) joint pairs. Pair index p = 2*i (+0/+1);
// joint = p % 25. Joints 0..7 rotate: out = x @ R with R=[[c,-s],[s,c]]
//   => ox = x*c + y*s ; oy = -x*s + y*c.

__global__ void __launch_bounds__(256)
rigid_rot_kernel(const float4* __restrict__ xin,
                 const float*  __restrict__ w,
                 float4* __restrict__ out,
                 unsigned n4)
{
    unsigned i = blockIdx.x * 256u + threadIdx.x;
    if (i >= n4) return;

    float s, c;
    sincosf(__ldg(w), &s, &c);

    float4 v = xin[i];

    unsigned p0 = 2u * i;            // joint-pair index of (v.x, v.y)
    unsigned j0 = p0 % 25u;          // const-divisor -> mul-hi sequence
    unsigned j1 = (j0 + 1u == 25u) ? 0u : (j0 + 1u);

    if (j0 < 8u) {
        float nx =  fmaf(v.x, c, v.y * s);
        float ny =  fmaf(v.y, c, -v.x * s);
        v.x = nx; v.y = ny;
    }
    if (j1 < 8u) {
        float nx =  fmaf(v.z, c, v.w * s);
        float ny =  fmaf(v.w, c, -v.z * s);
        v.z = nx; v.w = ny;
    }

    out[i] = v;
}

extern "C" void kernel_launch(void* const* d_in, const int* in_sizes, int n_in,
                              void* d_out, int out_size)
{
    const float4* x = (const float4*)d_in[0];
    const float*  w = (const float*)d_in[1];
    float4* out = (float4*)d_out;

    unsigned n4 = (unsigned)(out_size / 4);   // 6,553,600
    unsigned blocks = (n4 + 255u) / 256u;

    rigid_rot_kernel<<<blocks, 256>>>(x, w, out, n4);
}